// round 15
// baseline (speedup 1.0000x reference)
#include <cuda_runtime.h>
#include <cuda_fp16.h>
#include <stdint.h>

#define DIM 512
#define NHEADS 8
#define HD 64
#define BB 2
#define SS 2048
#define MROWS (BB*SS)   // 4096

// Scratch (static device allocation — allowed)
__device__ half g_xh[MROWS * DIM];
__device__ half g_qeh[MROWS * DIM];
__device__ half g_keh[MROWS * DIM];
__device__ half g_Wh[4][DIM * DIM];      // Wq, Wk, Wv, Wo as half
__device__ half g_Qh[MROWS * DIM];       // Q proj (pre-scaled by 0.125*log2e)
__device__ half g_Kh[MROWS * DIM];
__device__ half g_Vth[DIM * MROWS];      // V proj TRANSPOSED [dim][token]
__device__ half g_Ah[MROWS * DIM];       // attention output (half)

// ---------------------------------------------------------------------------
// helpers
// ---------------------------------------------------------------------------
__device__ __forceinline__ void mma_f16(float c[4],
                                        uint32_t a0, uint32_t a1, uint32_t a2, uint32_t a3,
                                        uint32_t b0, uint32_t b1) {
    asm volatile(
        "mma.sync.aligned.m16n8k16.row.col.f32.f16.f16.f32 "
        "{%0,%1,%2,%3}, {%4,%5,%6,%7}, {%8,%9}, {%0,%1,%2,%3};"
        : "+f"(c[0]), "+f"(c[1]), "+f"(c[2]), "+f"(c[3])
        : "r"(a0), "r"(a1), "r"(a2), "r"(a3), "r"(b0), "r"(b1));
}

__device__ __forceinline__ uint32_t h2u(half2 h) { return *(uint32_t*)&h; }

__device__ __forceinline__ uint2 f4h4(float4 v) {
    half2 lo = __floats2half2_rn(v.x, v.y);
    half2 hi = __floats2half2_rn(v.z, v.w);
    return make_uint2(h2u(lo), h2u(hi));
}

__device__ __forceinline__ float ex2(float x) {
    float y;
    asm("ex2.approx.ftz.f32 %0, %1;" : "=f"(y) : "f"(x));
    return y;
}

// packed fp16x2 exp2: one MUFU op for two exponentials
__device__ __forceinline__ uint32_t ex2h2(uint32_t x) {
    uint32_t y;
    asm("ex2.approx.f16x2 %0, %1;" : "=r"(y) : "r"(x));
    return y;
}

__device__ __forceinline__ void ldm4(uint32_t addr, uint32_t& r0, uint32_t& r1,
                                     uint32_t& r2, uint32_t& r3) {
    asm volatile("ldmatrix.sync.aligned.m8n8.x4.shared.b16 {%0,%1,%2,%3}, [%4];"
                 : "=r"(r0), "=r"(r1), "=r"(r2), "=r"(r3) : "r"(addr));
}

#define CP16(dst, src) \
    asm volatile("cp.async.cg.shared.global [%0], [%1], 16;" :: "r"(dst), "l"(src))
#define CP_COMMIT() asm volatile("cp.async.commit_group;")
#define CP_WAIT1()  asm volatile("cp.async.wait_group 1;")
#define CP_WAIT0()  asm volatile("cp.async.wait_group 0;")

// rows of 128B = 8 chunks of 16B, XOR-swizzled by row&7.
__device__ __forceinline__ uint32_t swb(int r, int c8) {
    return (uint32_t)(r * 128 + ((c8 ^ (r & 7)) << 4));
}

// ---------------------------------------------------------------------------
// fp32 -> fp16 conversion, 7 planes (single fused launch, big grid)
// ---------------------------------------------------------------------------
struct CvtArgs {
    const float* s[7];
    half* d[7];
    int n4[7];
};

__global__ __launch_bounds__(256) void cvt_all(CvtArgs a) {
    int z = blockIdx.y;
    int n4 = a.n4[z];
    const float4* s = (const float4*)a.s[z];
    half* d = a.d[z];
    for (int i = blockIdx.x * blockDim.x + threadIdx.x; i < n4;
         i += gridDim.x * blockDim.x) {
        float4 v = s[i];
        *(uint2*)(d + (size_t)i * 4) = f4h4(v);
    }
}

// ---------------------------------------------------------------------------
// C[M,N] = A[M,K] @ W[N,K]^T + bias  (NT, half in, fp16 mma).
// 128 x NTILE tile, 256 thr, 64-deep k chunks, 3-stage cp.async pipeline,
// ONE barrier per chunk.
// ---------------------------------------------------------------------------
template<int NTILE>
__device__ __forceinline__ void gemm_body(const half* __restrict__ A,
                                          const half* __restrict__ W,
                                          const float* __restrict__ bias,
                                          float scale,
                                          float* Cf, half* Ch, half* Ct,
                                          int row0, int col0, half* smem) {
    const int tid = threadIdx.x;
    const int w = tid >> 5, lane = tid & 31;
    const int tig = lane & 3, lg = lane >> 2;
    const int m = lane >> 3, l7 = lane & 7;
    const int wr = w & 3;
    const int wc = w >> 2;
    constexpr int JP = NTILE / 32;
    constexpr uint32_t STG = 16384 + (uint32_t)NTILE * 128;

    uint32_t sbase = (uint32_t)__cvta_generic_to_shared(smem);
    uint32_t sA[3], sW[3];
#pragma unroll
    for (int s = 0; s < 3; s++) { sA[s] = sbase + s * STG; sW[s] = sA[s] + 16384; }

    float acc[2][2 * JP][4];
#pragma unroll
    for (int g = 0; g < 2; g++)
#pragma unroll
        for (int j = 0; j < 2 * JP; j++)
#pragma unroll
            for (int i = 0; i < 4; i++) acc[g][j][i] = 0.f;

    auto load_stage = [&](int si, int kc) {
#pragma unroll
        for (int i = 0; i < 4; i++) {
            int idx = tid + i * 256;
            int r = idx >> 3, c8 = idx & 7;
            CP16(sA[si] + swb(r, c8), A + (size_t)(row0 + r) * DIM + kc + c8 * 8);
        }
#pragma unroll
        for (int i = 0; i < NTILE / 32; i++) {
            int idx = tid + i * 256;
            int r = idx >> 3, c8 = idx & 7;
            CP16(sW[si] + swb(r, c8), W + (size_t)(col0 + r) * DIM + kc + c8 * 8);
        }
        CP_COMMIT();
    };

    load_stage(0, 0);
    load_stage(1, 64);
    for (int c = 0; c < 8; c++) {
        int si = c % 3;
        if (c < 7) { CP_WAIT1(); } else { CP_WAIT0(); }
        __syncthreads();
        if (c < 6) load_stage((c + 2) % 3, (c + 2) * 64);
#pragma unroll
        for (int ks = 0; ks < 4; ks++) {
            uint32_t af[2][4];
#pragma unroll
            for (int g = 0; g < 2; g++) {
                int rr = wr * 32 + g * 16 + ((m & 1) << 3) + l7;
                int c8 = ks * 2 + (m >> 1);
                ldm4(sA[si] + swb(rr, c8), af[g][0], af[g][1], af[g][2], af[g][3]);
            }
#pragma unroll
            for (int jp = 0; jp < JP; jp++) {
                uint32_t b0, b1, b2, b3;
                int rr = wc * (NTILE / 2) + (2 * jp + (m >> 1)) * 8 + l7;
                int c8 = ks * 2 + (m & 1);
                ldm4(sW[si] + swb(rr, c8), b0, b1, b2, b3);
#pragma unroll
                for (int g = 0; g < 2; g++) {
                    mma_f16(acc[g][2 * jp],     af[g][0], af[g][1], af[g][2], af[g][3], b0, b1);
                    mma_f16(acc[g][2 * jp + 1], af[g][0], af[g][1], af[g][2], af[g][3], b2, b3);
                }
            }
        }
    }

#pragma unroll
    for (int g = 0; g < 2; g++) {
        const int gr = row0 + wr * 32 + g * 16 + lg;
#pragma unroll
        for (int j = 0; j < 2 * JP; j++) {
            int c = col0 + wc * (NTILE / 2) + 8 * j + 2 * tig;
            float b0v = bias[c], b1v = bias[c + 1];
            float v0 = (acc[g][j][0] + b0v) * scale;
            float v1 = (acc[g][j][1] + b1v) * scale;
            float v2 = (acc[g][j][2] + b0v) * scale;
            float v3 = (acc[g][j][3] + b1v) * scale;
            if (Ch) {
                *(half2*)(Ch + (size_t)gr * DIM + c) = __floats2half2_rn(v0, v1);
                *(half2*)(Ch + (size_t)(gr + 8) * DIM + c) = __floats2half2_rn(v2, v3);
            } else if (Ct) {
                Ct[(size_t)c * MROWS + gr] = __float2half(v0);
                Ct[(size_t)(c + 1) * MROWS + gr] = __float2half(v1);
                Ct[(size_t)c * MROWS + gr + 8] = __float2half(v2);
                Ct[(size_t)(c + 1) * MROWS + gr + 8] = __float2half(v3);
            } else {
                *(float2*)(Cf + (size_t)gr * DIM + c) = make_float2(v0, v1);
                *(float2*)(Cf + (size_t)(gr + 8) * DIM + c) = make_float2(v2, v3);
            }
        }
    }
}

#define QKV_SMEM (3 * (16384 + 128 * 128))   // 98304
#define O_SMEM   (3 * (16384 + 64 * 128))    // 73728
#define ATTN_SMEM 65536
#define QSCALE   0.18033688011112042f        // 0.125 * log2(e)

__global__ __launch_bounds__(256, 2) void gemm_qkv(const float* __restrict__ bq,
                                                   const float* __restrict__ bk,
                                                   const float* __restrict__ bv) {
    extern __shared__ __align__(16) half smem[];
    int z = blockIdx.z;
    const half* A = (z == 0) ? g_qeh : (z == 1) ? g_keh : g_xh;
    const half* W = g_Wh[z];
    const float* bias = (z == 0) ? bq : (z == 1) ? bk : bv;
    float scale = (z == 0) ? QSCALE : 1.0f;
    half* Ch = (z == 0) ? g_Qh : (z == 1) ? g_Kh : nullptr;
    half* Ct = (z == 2) ? g_Vth : nullptr;
    gemm_body<128>(A, W, bias, scale, nullptr, Ch, Ct,
                   blockIdx.y * 128, blockIdx.x * 128, smem);
}

// 3 CTAs/SM: 3 x 24KB smem = 216KB < 228KB; regs clamped to 85.
__global__ __launch_bounds__(256, 3) void gemm_o(const float* __restrict__ bo,
                                                 float* __restrict__ out) {
    extern __shared__ __align__(16) half smem[];
    gemm_body<64>(g_Ah, g_Wh[3], bo, 1.0f, out, nullptr, nullptr,
                  blockIdx.y * 128, blockIdx.x * 64, smem);
}

// ---------------------------------------------------------------------------
// Flash attention: 256 queries/block, 512 thr (16 warps x 16 rows), fp16 mma.
// 128-KEY stages (K 16KB + V^T 16KB), 2-stage cp.async pipeline, ONE barrier
// per 128 keys. Packed fp16x2 max-shuffle (2 shfls) and PACKED fp16x2 exp2
// (halves MUFU ops; exp output feeds PV mma directly). grid = (S/256, H, B).
// ---------------------------------------------------------------------------
__global__ __launch_bounds__(512, 1) void attn_f16(float* __restrict__ dummy) {
    extern __shared__ __align__(16) half asmem[];   // 2 x (16KB K + 16KB V)

    const int tid = threadIdx.x;
    const int w = tid >> 5, lane = tid & 31;
    const int tig = lane & 3, lg = lane >> 2;
    const int m = lane >> 3, l7 = lane & 7;
    const int q0 = blockIdx.x * 256;
    const int h = blockIdx.y;
    const int b = blockIdx.z;
    const size_t qbase = (size_t)(b * SS + q0) * DIM + h * HD;
    const int rA = 16 * w + lg;     // 0..255

    uint32_t base = (uint32_t)__cvta_generic_to_shared(asmem);
    uint32_t sK[2], sV[2];
#pragma unroll
    for (int s = 0; s < 2; s++) { sK[s] = base + s * 32768u; sV[s] = sK[s] + 16384u; }

    auto load_kv = [&](int si, int kt) {
        const size_t kbase = (size_t)(b * SS + kt) * DIM + h * HD;
#pragma unroll
        for (int i = 0; i < 2; i++) {                 // K: 128 rows x 8 chunks
            int idx = tid + i * 512;
            int r = idx >> 3, c8 = idx & 7;
            CP16(sK[si] + swb(r, c8), g_Kh + kbase + (size_t)r * DIM + c8 * 8);
        }
#pragma unroll
        for (int i = 0; i < 2; i++) {                 // V^T: 2 subtiles x 64 rows x 8
            int idx = tid + i * 512;
            int sub = idx >> 9, rem = idx & 511;
            int r = rem >> 3, c8 = rem & 7;
            CP16(sV[si] + sub * 8192u + swb(r, c8),
                 g_Vth + (size_t)(h * HD + r) * MROWS + b * SS + kt + sub * 64 + c8 * 8);
        }
        CP_COMMIT();
    };

    // ---- issue stage-0 K/V load, then stage Q (256 rows = 32KB) via stage-1
    load_kv(0, 0);
#pragma unroll
    for (int i = 0; i < 4; i++) {
        int idx = tid + i * 512;
        int r = idx >> 3, c8 = idx & 7;
        CP16(sK[1] + swb(r, c8), g_Qh + qbase + (size_t)r * DIM + c8 * 8);
    }
    CP_COMMIT();
    CP_WAIT0();
    __syncthreads();
    uint32_t qfr[4][4];
#pragma unroll
    for (int ks = 0; ks < 4; ks++) {
        int rr = 16 * w + ((m & 1) << 3) + l7;
        int c8 = ks * 2 + (m >> 1);
        ldm4(sK[1] + swb(rr, c8), qfr[ks][0], qfr[ks][1], qfr[ks][2], qfr[ks][3]);
    }

    float o[8][4];
#pragma unroll
    for (int j = 0; j < 8; j++)
#pragma unroll
        for (int i = 0; i < 4; i++) o[j][i] = 0.f;
    float mA = -60000.f, mB = -60000.f, lsA = 0.f, lsB = 0.f;

    for (int t = 0; t < SS / 128; t++) {
        int si = t & 1;
        if (t > 0) { if (t < SS / 128 - 1) { CP_WAIT1(); } else { CP_WAIT0(); } }
        __syncthreads();
        if (t < SS / 128 - 1) load_kv(1 - si, (t + 1) * 128);

#pragma unroll
        for (int cc = 0; cc < 2; cc++) {              // two 64-key halves
            // --- S = Q K^T (log2e-scaled domain)
            float s[8][4];
#pragma unroll
            for (int j = 0; j < 8; j++)
#pragma unroll
                for (int i = 0; i < 4; i++) s[j][i] = 0.f;
#pragma unroll
            for (int ks = 0; ks < 4; ks++) {
#pragma unroll
                for (int jp = 0; jp < 4; jp++) {
                    uint32_t b0, b1, b2, b3;
                    int rr = 64 * cc + (2 * jp + (m >> 1)) * 8 + l7;
                    int c8 = ks * 2 + (m & 1);
                    ldm4(sK[si] + swb(rr, c8), b0, b1, b2, b3);
                    mma_f16(s[2 * jp],     qfr[ks][0], qfr[ks][1], qfr[ks][2], qfr[ks][3], b0, b1);
                    mma_f16(s[2 * jp + 1], qfr[ks][0], qfr[ks][1], qfr[ks][2], qfr[ks][3], b2, b3);
                }
            }

            // --- online softmax (packed fp16x2 max reduce: 2 shfls)
            float tA = mA, tB = mB;
#pragma unroll
            for (int j = 0; j < 8; j++) {
                tA = fmaxf(tA, fmaxf(s[j][0], s[j][1]));
                tB = fmaxf(tB, fmaxf(s[j][2], s[j][3]));
            }
            half2 t2 = __floats2half2_rn(tA, tB);
            {
                uint32_t u = h2u(t2);
                uint32_t v1 = __shfl_xor_sync(0xffffffffu, u, 1);
                t2 = __hmax2(t2, *(half2*)&v1);
                u = h2u(t2);
                uint32_t v2 = __shfl_xor_sync(0xffffffffu, u, 2);
                t2 = __hmax2(t2, *(half2*)&v2);
            }
            tA = __low2float(t2); tB = __high2float(t2);
            float cA = ex2(mA - tA), cB = ex2(mB - tB);
            mA = tA; mB = tB;

            // --- packed fp16 exp2: peA[j] = exp2(sA-pair), peB[j] = exp2(sB-pair)
            uint32_t peA[8], peB[8];
            float sA = 0.f, sB = 0.f;
#pragma unroll
            for (int j = 0; j < 8; j++) {
                peA[j] = ex2h2(h2u(__floats2half2_rn(s[j][0] - tA, s[j][1] - tA)));
                peB[j] = ex2h2(h2u(__floats2half2_rn(s[j][2] - tB, s[j][3] - tB)));
                float2 fa = __half22float2(*(half2*)&peA[j]);
                float2 fb = __half22float2(*(half2*)&peB[j]);
                sA += fa.x + fa.y;
                sB += fb.x + fb.y;
            }
            lsA = lsA * cA + sA;
            lsB = lsB * cB + sB;
            if (cA != 1.f || cB != 1.f) {
#pragma unroll
                for (int j = 0; j < 8; j++) {
                    o[j][0] *= cA; o[j][1] *= cA; o[j][2] *= cB; o[j][3] *= cB;
                }
            }

            // --- O += P V  (P = packed exp results, V^T subtile cc)
#pragma unroll
            for (int kk = 0; kk < 4; kk++) {
#pragma unroll
                for (int jp = 0; jp < 4; jp++) {
                    uint32_t b0, b1, b2, b3;
                    int rr = (2 * jp + (m >> 1)) * 8 + l7;
                    int c8 = kk * 2 + (m & 1);
                    ldm4(sV[si] + cc * 8192u + swb(rr, c8), b0, b1, b2, b3);
                    mma_f16(o[2 * jp],     peA[2 * kk], peB[2 * kk],
                            peA[2 * kk + 1], peB[2 * kk + 1], b0, b1);
                    mma_f16(o[2 * jp + 1], peA[2 * kk], peB[2 * kk],
                            peA[2 * kk + 1], peB[2 * kk + 1], b2, b3);
                }
            }
        }
    }

    // deferred softmax-sum reduction (quad lanes share a row)
    lsA += __shfl_xor_sync(0xffffffffu, lsA, 1);
    lsA += __shfl_xor_sync(0xffffffffu, lsA, 2);
    lsB += __shfl_xor_sync(0xffffffffu, lsB, 1);
    lsB += __shfl_xor_sync(0xffffffffu, lsB, 2);

    const float iA = 1.f / lsA, iB = 1.f / lsB;
#pragma unroll
    for (int j = 0; j < 8; j++) {
        int c = 8 * j + 2 * tig;
        *(half2*)(g_Ah + qbase + (size_t)rA * DIM + c) =
            __floats2half2_rn(o[j][0] * iA, o[j][1] * iA);
        *(half2*)(g_Ah + qbase + (size_t)(rA + 8) * DIM + c) =
            __floats2half2_rn(o[j][2] * iB, o[j][3] * iB);
    }
}

// ---------------------------------------------------------------------------
// Launch. Inputs: x, Qexpl, Kexpl, fl, fu, age, gender,
//                 Wq, bq, Wk, bk, Wv, bv, Wo, bo
// ---------------------------------------------------------------------------
extern "C" void kernel_launch(void* const* d_in, const int* in_sizes, int n_in,
                              void* d_out, int out_size) {
    const float* x     = (const float*)d_in[0];
    const float* Qexpl = (const float*)d_in[1];
    const float* Kexpl = (const float*)d_in[2];
    const float* Wq = (const float*)d_in[7];
    const float* bq = (const float*)d_in[8];
    const float* Wk = (const float*)d_in[9];
    const float* bk = (const float*)d_in[10];
    const float* Wv = (const float*)d_in[11];
    const float* bv = (const float*)d_in[12];
    const float* Wo = (const float*)d_in[13];
    const float* bo = (const float*)d_in[14];
    float* out = (float*)d_out;

    half *pxh, *pqeh, *pkeh, *pWh;
    cudaGetSymbolAddress((void**)&pxh, g_xh);
    cudaGetSymbolAddress((void**)&pqeh, g_qeh);
    cudaGetSymbolAddress((void**)&pkeh, g_keh);
    cudaGetSymbolAddress((void**)&pWh, g_Wh);

    static int smem_set = 0;
    if (!smem_set) {
        cudaFuncSetAttribute(gemm_qkv, cudaFuncAttributeMaxDynamicSharedMemorySize, QKV_SMEM);
        cudaFuncSetAttribute(gemm_o, cudaFuncAttributeMaxDynamicSharedMemorySize, O_SMEM);
        cudaFuncSetAttribute(attn_f16, cudaFuncAttributeMaxDynamicSharedMemorySize, ATTN_SMEM);
        smem_set = 1;
    }

    CvtArgs ca;
    ca.s[0] = x;     ca.d[0] = pxh;                 ca.n4[0] = MROWS * DIM / 4;
    ca.s[1] = Qexpl; ca.d[1] = pqeh;                ca.n4[1] = MROWS * DIM / 4;
    ca.s[2] = Kexpl; ca.d[2] = pkeh;                ca.n4[2] = MROWS * DIM / 4;
    ca.s[3] = Wq;    ca.d[3] = pWh;                 ca.n4[3] = DIM * DIM / 4;
    ca.s[4] = Wk;    ca.d[4] = pWh + DIM * DIM;     ca.n4[4] = DIM * DIM / 4;
    ca.s[5] = Wv;    ca.d[5] = pWh + 2 * DIM * DIM; ca.n4[5] = DIM * DIM / 4;
    ca.s[6] = Wo;    ca.d[6] = pWh + 3 * DIM * DIM; ca.n4[6] = DIM * DIM / 4;
    cvt_all<<<dim3(256, 7), 256>>>(ca);

    dim3 qkvgrid(DIM / 128, MROWS / 128, 3);
    gemm_qkv<<<qkvgrid, 256, QKV_SMEM>>>(bq, bk, bv);

    dim3 agrid(SS / 256, NHEADS, BB);
    attn_f16<<<agrid, 512, ATTN_SMEM>>>(nullptr);

    dim3 ogrid(DIM / 64, MROWS / 128);
    gemm_o<<<ogrid, 256, O_SMEM>>>(bo, out);
}

// round 17
// speedup vs baseline: 1.0131x; 1.0131x over previous
#include <cuda_runtime.h>
#include <cuda_fp16.h>
#include <stdint.h>

#define DIM 512
#define NHEADS 8
#define HD 64
#define BB 2
#define SS 2048
#define MROWS (BB*SS)   // 4096

// Scratch (static device allocation — allowed)
__device__ half g_xh[MROWS * DIM];
__device__ half g_qeh[MROWS * DIM];
__device__ half g_keh[MROWS * DIM];
__device__ half g_Wh[4][DIM * DIM];      // Wq, Wk, Wv, Wo as half
__device__ half g_Qh[MROWS * DIM];       // Q proj (pre-scaled by 0.125*log2e)
__device__ half g_Kh[MROWS * DIM];
__device__ half g_Vth[DIM * MROWS];      // V proj TRANSPOSED [dim][token]
__device__ half g_Ah[MROWS * DIM];       // attention output (half)

// ---------------------------------------------------------------------------
// helpers
// ---------------------------------------------------------------------------
__device__ __forceinline__ void mma_f16(float c[4],
                                        uint32_t a0, uint32_t a1, uint32_t a2, uint32_t a3,
                                        uint32_t b0, uint32_t b1) {
    asm volatile(
        "mma.sync.aligned.m16n8k16.row.col.f32.f16.f16.f32 "
        "{%0,%1,%2,%3}, {%4,%5,%6,%7}, {%8,%9}, {%0,%1,%2,%3};"
        : "+f"(c[0]), "+f"(c[1]), "+f"(c[2]), "+f"(c[3])
        : "r"(a0), "r"(a1), "r"(a2), "r"(a3), "r"(b0), "r"(b1));
}

__device__ __forceinline__ uint32_t h2u(half2 h) { return *(uint32_t*)&h; }

__device__ __forceinline__ uint2 f4h4(float4 v) {
    half2 lo = __floats2half2_rn(v.x, v.y);
    half2 hi = __floats2half2_rn(v.z, v.w);
    return make_uint2(h2u(lo), h2u(hi));
}

__device__ __forceinline__ float ex2(float x) {
    float y;
    asm("ex2.approx.ftz.f32 %0, %1;" : "=f"(y) : "f"(x));
    return y;
}

__device__ __forceinline__ void ldm4(uint32_t addr, uint32_t& r0, uint32_t& r1,
                                     uint32_t& r2, uint32_t& r3) {
    asm volatile("ldmatrix.sync.aligned.m8n8.x4.shared.b16 {%0,%1,%2,%3}, [%4];"
                 : "=r"(r0), "=r"(r1), "=r"(r2), "=r"(r3) : "r"(addr));
}

#define CP16(dst, src) \
    asm volatile("cp.async.cg.shared.global [%0], [%1], 16;" :: "r"(dst), "l"(src))
#define CP_COMMIT() asm volatile("cp.async.commit_group;")
#define CP_WAIT1()  asm volatile("cp.async.wait_group 1;")
#define CP_WAIT0()  asm volatile("cp.async.wait_group 0;")

// rows of 128B = 8 chunks of 16B, XOR-swizzled by row&7.
__device__ __forceinline__ uint32_t swb(int r, int c8) {
    return (uint32_t)(r * 128 + ((c8 ^ (r & 7)) << 4));
}

// ---------------------------------------------------------------------------
// fp32 -> fp16 conversion, 7 planes (single fused launch, big grid)
// ---------------------------------------------------------------------------
struct CvtArgs {
    const float* s[7];
    half* d[7];
    int n4[7];
};

__global__ __launch_bounds__(256) void cvt_all(CvtArgs a) {
    int z = blockIdx.y;
    int n4 = a.n4[z];
    const float4* s = (const float4*)a.s[z];
    half* d = a.d[z];
    for (int i = blockIdx.x * blockDim.x + threadIdx.x; i < n4;
         i += gridDim.x * blockDim.x) {
        float4 v = s[i];
        *(uint2*)(d + (size_t)i * 4) = f4h4(v);
    }
}

// ---------------------------------------------------------------------------
// C[M,N] = A[M,K] @ W[N,K]^T + bias  (NT, half in, fp16 mma).
// 128 x NTILE tile, 256 thr, 64-deep k chunks, 3-stage cp.async pipeline,
// ONE barrier per chunk.
// ---------------------------------------------------------------------------
template<int NTILE>
__device__ __forceinline__ void gemm_body(const half* __restrict__ A,
                                          const half* __restrict__ W,
                                          const float* __restrict__ bias,
                                          float scale,
                                          float* Cf, half* Ch, half* Ct,
                                          int row0, int col0, half* smem) {
    const int tid = threadIdx.x;
    const int w = tid >> 5, lane = tid & 31;
    const int tig = lane & 3, lg = lane >> 2;
    const int m = lane >> 3, l7 = lane & 7;
    const int wr = w & 3;
    const int wc = w >> 2;
    constexpr int JP = NTILE / 32;
    constexpr uint32_t STG = 16384 + (uint32_t)NTILE * 128;

    uint32_t sbase = (uint32_t)__cvta_generic_to_shared(smem);
    uint32_t sA[3], sW[3];
#pragma unroll
    for (int s = 0; s < 3; s++) { sA[s] = sbase + s * STG; sW[s] = sA[s] + 16384; }

    float acc[2][2 * JP][4];
#pragma unroll
    for (int g = 0; g < 2; g++)
#pragma unroll
        for (int j = 0; j < 2 * JP; j++)
#pragma unroll
            for (int i = 0; i < 4; i++) acc[g][j][i] = 0.f;

    auto load_stage = [&](int si, int kc) {
#pragma unroll
        for (int i = 0; i < 4; i++) {
            int idx = tid + i * 256;
            int r = idx >> 3, c8 = idx & 7;
            CP16(sA[si] + swb(r, c8), A + (size_t)(row0 + r) * DIM + kc + c8 * 8);
        }
#pragma unroll
        for (int i = 0; i < NTILE / 32; i++) {
            int idx = tid + i * 256;
            int r = idx >> 3, c8 = idx & 7;
            CP16(sW[si] + swb(r, c8), W + (size_t)(col0 + r) * DIM + kc + c8 * 8);
        }
        CP_COMMIT();
    };

    load_stage(0, 0);
    load_stage(1, 64);
    for (int c = 0; c < 8; c++) {
        int si = c % 3;
        if (c < 7) { CP_WAIT1(); } else { CP_WAIT0(); }
        __syncthreads();
        if (c < 6) load_stage((c + 2) % 3, (c + 2) * 64);
#pragma unroll
        for (int ks = 0; ks < 4; ks++) {
            uint32_t af[2][4];
#pragma unroll
            for (int g = 0; g < 2; g++) {
                int rr = wr * 32 + g * 16 + ((m & 1) << 3) + l7;
                int c8 = ks * 2 + (m >> 1);
                ldm4(sA[si] + swb(rr, c8), af[g][0], af[g][1], af[g][2], af[g][3]);
            }
#pragma unroll
            for (int jp = 0; jp < JP; jp++) {
                uint32_t b0, b1, b2, b3;
                int rr = wc * (NTILE / 2) + (2 * jp + (m >> 1)) * 8 + l7;
                int c8 = ks * 2 + (m & 1);
                ldm4(sW[si] + swb(rr, c8), b0, b1, b2, b3);
#pragma unroll
                for (int g = 0; g < 2; g++) {
                    mma_f16(acc[g][2 * jp],     af[g][0], af[g][1], af[g][2], af[g][3], b0, b1);
                    mma_f16(acc[g][2 * jp + 1], af[g][0], af[g][1], af[g][2], af[g][3], b2, b3);
                }
            }
        }
    }

#pragma unroll
    for (int g = 0; g < 2; g++) {
        const int gr = row0 + wr * 32 + g * 16 + lg;
#pragma unroll
        for (int j = 0; j < 2 * JP; j++) {
            int c = col0 + wc * (NTILE / 2) + 8 * j + 2 * tig;
            float b0v = bias[c], b1v = bias[c + 1];
            float v0 = (acc[g][j][0] + b0v) * scale;
            float v1 = (acc[g][j][1] + b1v) * scale;
            float v2 = (acc[g][j][2] + b0v) * scale;
            float v3 = (acc[g][j][3] + b1v) * scale;
            if (Ch) {
                *(half2*)(Ch + (size_t)gr * DIM + c) = __floats2half2_rn(v0, v1);
                *(half2*)(Ch + (size_t)(gr + 8) * DIM + c) = __floats2half2_rn(v2, v3);
            } else if (Ct) {
                Ct[(size_t)c * MROWS + gr] = __float2half(v0);
                Ct[(size_t)(c + 1) * MROWS + gr] = __float2half(v1);
                Ct[(size_t)c * MROWS + gr + 8] = __float2half(v2);
                Ct[(size_t)(c + 1) * MROWS + gr + 8] = __float2half(v3);
            } else {
                *(float2*)(Cf + (size_t)gr * DIM + c) = make_float2(v0, v1);
                *(float2*)(Cf + (size_t)(gr + 8) * DIM + c) = make_float2(v2, v3);
            }
        }
    }
}

#define QKV_SMEM (3 * (16384 + 128 * 128))   // 98304
#define O_SMEM   (3 * (16384 + 64 * 128))    // 73728
#define ATTN_SMEM (3 * 32768)                // 98304 (3-stage K/V)
#define QSCALE   0.18033688011112042f        // 0.125 * log2(e)

__global__ __launch_bounds__(256, 2) void gemm_qkv(const float* __restrict__ bq,
                                                   const float* __restrict__ bk,
                                                   const float* __restrict__ bv) {
    extern __shared__ __align__(16) half smem[];
    int z = blockIdx.z;
    const half* A = (z == 0) ? g_qeh : (z == 1) ? g_keh : g_xh;
    const half* W = g_Wh[z];
    const float* bias = (z == 0) ? bq : (z == 1) ? bk : bv;
    float scale = (z == 0) ? QSCALE : 1.0f;
    half* Ch = (z == 0) ? g_Qh : (z == 1) ? g_Kh : nullptr;
    half* Ct = (z == 2) ? g_Vth : nullptr;
    gemm_body<128>(A, W, bias, scale, nullptr, Ch, Ct,
                   blockIdx.y * 128, blockIdx.x * 128, smem);
}

// 3 CTAs/SM target: 3 x 24KB smem; carveout hint set host-side.
__global__ __launch_bounds__(256, 3) void gemm_o(const float* __restrict__ bo,
                                                 float* __restrict__ out) {
    extern __shared__ __align__(16) half smem[];
    gemm_body<64>(g_Ah, g_Wh[3], bo, 1.0f, out, nullptr, nullptr,
                  blockIdx.y * 128, blockIdx.x * 64, smem);
}

// ---------------------------------------------------------------------------
// Flash attention: 256 queries/block, 512 thr (16 warps x 16 rows), fp16 mma.
// 128-KEY stages (K 16KB + V^T 16KB), 3-stage cp.async pipeline with the
// SAME schedule as gemm_body: wait(t) -> sync -> load(t+2) -> compute(t).
// Packed fp16x2 max-shuffle; fp32 MUFU exps. grid = (S/256, H, B).
// ---------------------------------------------------------------------------
__global__ __launch_bounds__(512, 1) void attn_f16(float* __restrict__ dummy) {
    extern __shared__ __align__(16) half asmem[];   // 3 x (16KB K + 16KB V)

    const int tid = threadIdx.x;
    const int w = tid >> 5, lane = tid & 31;
    const int tig = lane & 3, lg = lane >> 2;
    const int m = lane >> 3, l7 = lane & 7;
    const int q0 = blockIdx.x * 256;
    const int h = blockIdx.y;
    const int b = blockIdx.z;
    const size_t qbase = (size_t)(b * SS + q0) * DIM + h * HD;
    const int rA = 16 * w + lg;     // 0..255

    uint32_t base = (uint32_t)__cvta_generic_to_shared(asmem);
    uint32_t sK[3], sV[3];
#pragma unroll
    for (int s = 0; s < 3; s++) { sK[s] = base + s * 32768u; sV[s] = sK[s] + 16384u; }

    auto load_kv = [&](int si, int kt) {
        const size_t kbase = (size_t)(b * SS + kt) * DIM + h * HD;
#pragma unroll
        for (int i = 0; i < 2; i++) {                 // K: 128 rows x 8 chunks
            int idx = tid + i * 512;
            int r = idx >> 3, c8 = idx & 7;
            CP16(sK[si] + swb(r, c8), g_Kh + kbase + (size_t)r * DIM + c8 * 8);
        }
#pragma unroll
        for (int i = 0; i < 2; i++) {                 // V^T: 2 subtiles x 64 rows x 8
            int idx = tid + i * 512;
            int sub = idx >> 9, rem = idx & 511;
            int r = rem >> 3, c8 = rem & 7;
            CP16(sV[si] + sub * 8192u + swb(r, c8),
                 g_Vth + (size_t)(h * HD + r) * MROWS + b * SS + kt + sub * 64 + c8 * 8);
        }
        CP_COMMIT();
    };

    // ---- prologue: Q (32KB) via stage-2, then tiles 0 and 1.
#pragma unroll
    for (int i = 0; i < 4; i++) {
        int idx = tid + i * 512;
        int r = idx >> 3, c8 = idx & 7;
        CP16(sK[2] + swb(r, c8), g_Qh + qbase + (size_t)r * DIM + c8 * 8);
    }
    CP_COMMIT();
    load_kv(0, 0);
    CP_WAIT1();                 // Q complete (kv0 may still be in flight)
    __syncthreads();
    uint32_t qfr[4][4];
#pragma unroll
    for (int ks = 0; ks < 4; ks++) {
        int rr = 16 * w + ((m & 1) << 3) + l7;
        int c8 = ks * 2 + (m >> 1);
        ldm4(sK[2] + swb(rr, c8), qfr[ks][0], qfr[ks][1], qfr[ks][2], qfr[ks][3]);
    }
    __syncthreads();            // all warps done reading stage-2 before reuse
    load_kv(1, 128);

    float o[8][4];
#pragma unroll
    for (int j = 0; j < 8; j++)
#pragma unroll
        for (int i = 0; i < 4; i++) o[j][i] = 0.f;
    float mA = -60000.f, mB = -60000.f, lsA = 0.f, lsB = 0.f;

    const int NT = SS / 128;    // 16 tiles
    for (int t = 0; t < NT; t++) {
        int si = t % 3;
        if (t < NT - 1) { CP_WAIT1(); } else { CP_WAIT0(); }
        __syncthreads();        // tile t ready; stage (t-1)%3 fully consumed
        if (t + 2 < NT) load_kv((t + 2) % 3, (t + 2) * 128);  // stage (t-1)%3

#pragma unroll
        for (int cc = 0; cc < 2; cc++) {              // two 64-key halves
            // --- S = Q K^T (log2e-scaled domain)
            float s[8][4];
#pragma unroll
            for (int j = 0; j < 8; j++)
#pragma unroll
                for (int i = 0; i < 4; i++) s[j][i] = 0.f;
#pragma unroll
            for (int ks = 0; ks < 4; ks++) {
#pragma unroll
                for (int jp = 0; jp < 4; jp++) {
                    uint32_t b0, b1, b2, b3;
                    int rr = 64 * cc + (2 * jp + (m >> 1)) * 8 + l7;
                    int c8 = ks * 2 + (m & 1);
                    ldm4(sK[si] + swb(rr, c8), b0, b1, b2, b3);
                    mma_f16(s[2 * jp],     qfr[ks][0], qfr[ks][1], qfr[ks][2], qfr[ks][3], b0, b1);
                    mma_f16(s[2 * jp + 1], qfr[ks][0], qfr[ks][1], qfr[ks][2], qfr[ks][3], b2, b3);
                }
            }

            // --- online softmax (packed fp16x2 max reduce: 2 shfls)
            float tA = mA, tB = mB;
#pragma unroll
            for (int j = 0; j < 8; j++) {
                tA = fmaxf(tA, fmaxf(s[j][0], s[j][1]));
                tB = fmaxf(tB, fmaxf(s[j][2], s[j][3]));
            }
            half2 t2 = __floats2half2_rn(tA, tB);
            {
                uint32_t u = h2u(t2);
                uint32_t v1 = __shfl_xor_sync(0xffffffffu, u, 1);
                t2 = __hmax2(t2, *(half2*)&v1);
                u = h2u(t2);
                uint32_t v2 = __shfl_xor_sync(0xffffffffu, u, 2);
                t2 = __hmax2(t2, *(half2*)&v2);
            }
            tA = __low2float(t2); tB = __high2float(t2);
            float cA = ex2(mA - tA), cB = ex2(mB - tB);
            mA = tA; mB = tB;
            float sA = 0.f, sB = 0.f;
#pragma unroll
            for (int j = 0; j < 8; j++) {
                s[j][0] = ex2(s[j][0] - tA);
                s[j][1] = ex2(s[j][1] - tA);
                s[j][2] = ex2(s[j][2] - tB);
                s[j][3] = ex2(s[j][3] - tB);
                sA += s[j][0] + s[j][1];
                sB += s[j][2] + s[j][3];
            }
            lsA = lsA * cA + sA;
            lsB = lsB * cB + sB;
#pragma unroll
            for (int j = 0; j < 8; j++) {
                o[j][0] *= cA; o[j][1] *= cA; o[j][2] *= cB; o[j][3] *= cB;
            }

            // --- O += P V  (V^T subtile cc; pack P per-kk)
#pragma unroll
            for (int kk = 0; kk < 4; kk++) {
                uint32_t pa0 = h2u(__floats2half2_rn(s[2 * kk][0], s[2 * kk][1]));
                uint32_t pa1 = h2u(__floats2half2_rn(s[2 * kk][2], s[2 * kk][3]));
                uint32_t pa2 = h2u(__floats2half2_rn(s[2 * kk + 1][0], s[2 * kk + 1][1]));
                uint32_t pa3 = h2u(__floats2half2_rn(s[2 * kk + 1][2], s[2 * kk + 1][3]));
#pragma unroll
                for (int jp = 0; jp < 4; jp++) {
                    uint32_t b0, b1, b2, b3;
                    int rr = (2 * jp + (m >> 1)) * 8 + l7;
                    int c8 = kk * 2 + (m & 1);
                    ldm4(sV[si] + cc * 8192u + swb(rr, c8), b0, b1, b2, b3);
                    mma_f16(o[2 * jp],     pa0, pa1, pa2, pa3, b0, b1);
                    mma_f16(o[2 * jp + 1], pa0, pa1, pa2, pa3, b2, b3);
                }
            }
        }
    }

    // deferred softmax-sum reduction (quad lanes share a row)
    lsA += __shfl_xor_sync(0xffffffffu, lsA, 1);
    lsA += __shfl_xor_sync(0xffffffffu, lsA, 2);
    lsB += __shfl_xor_sync(0xffffffffu, lsB, 1);
    lsB += __shfl_xor_sync(0xffffffffu, lsB, 2);

    const float iA = 1.f / lsA, iB = 1.f / lsB;
#pragma unroll
    for (int j = 0; j < 8; j++) {
        int c = 8 * j + 2 * tig;
        *(half2*)(g_Ah + qbase + (size_t)rA * DIM + c) =
            __floats2half2_rn(o[j][0] * iA, o[j][1] * iA);
        *(half2*)(g_Ah + qbase + (size_t)(rA + 8) * DIM + c) =
            __floats2half2_rn(o[j][2] * iB, o[j][3] * iB);
    }
}

// ---------------------------------------------------------------------------
// Launch. Inputs: x, Qexpl, Kexpl, fl, fu, age, gender,
//                 Wq, bq, Wk, bk, Wv, bv, Wo, bo
// ---------------------------------------------------------------------------
extern "C" void kernel_launch(void* const* d_in, const int* in_sizes, int n_in,
                              void* d_out, int out_size) {
    const float* x     = (const float*)d_in[0];
    const float* Qexpl = (const float*)d_in[1];
    const float* Kexpl = (const float*)d_in[2];
    const float* Wq = (const float*)d_in[7];
    const float* bq = (const float*)d_in[8];
    const float* Wk = (const float*)d_in[9];
    const float* bk = (const float*)d_in[10];
    const float* Wv = (const float*)d_in[11];
    const float* bv = (const float*)d_in[12];
    const float* Wo = (const float*)d_in[13];
    const float* bo = (const float*)d_in[14];
    float* out = (float*)d_out;

    half *pxh, *pqeh, *pkeh, *pWh;
    cudaGetSymbolAddress((void**)&pxh, g_xh);
    cudaGetSymbolAddress((void**)&pqeh, g_qeh);
    cudaGetSymbolAddress((void**)&pkeh, g_keh);
    cudaGetSymbolAddress((void**)&pWh, g_Wh);

    static int smem_set = 0;
    if (!smem_set) {
        cudaFuncSetAttribute(gemm_qkv, cudaFuncAttributeMaxDynamicSharedMemorySize, QKV_SMEM);
        cudaFuncSetAttribute(gemm_o, cudaFuncAttributeMaxDynamicSharedMemorySize, O_SMEM);
        cudaFuncSetAttribute(gemm_o, cudaFuncAttributePreferredSharedMemoryCarveout, 100);
        cudaFuncSetAttribute(attn_f16, cudaFuncAttributeMaxDynamicSharedMemorySize, ATTN_SMEM);
        smem_set = 1;
    }

    CvtArgs ca;
    ca.s[0] = x;     ca.d[0] = pxh;                 ca.n4[0] = MROWS * DIM / 4;
    ca.s[1] = Qexpl; ca.d[1] = pqeh;                ca.n4[1] = MROWS * DIM / 4;
    ca.s[2] = Kexpl; ca.d[2] = pkeh;                ca.n4[2] = MROWS * DIM / 4;
    ca.s[3] = Wq;    ca.d[3] = pWh;                 ca.n4[3] = DIM * DIM / 4;
    ca.s[4] = Wk;    ca.d[4] = pWh + DIM * DIM;     ca.n4[4] = DIM * DIM / 4;
    ca.s[5] = Wv;    ca.d[5] = pWh + 2 * DIM * DIM; ca.n4[5] = DIM * DIM / 4;
    ca.s[6] = Wo;    ca.d[6] = pWh + 3 * DIM * DIM; ca.n4[6] = DIM * DIM / 4;
    cvt_all<<<dim3(256, 7), 256>>>(ca);

    dim3 qkvgrid(DIM / 128, MROWS / 128, 3);
    gemm_qkv<<<qkvgrid, 256, QKV_SMEM>>>(bq, bk, bv);

    dim3 agrid(SS / 256, NHEADS, BB);
    attn_f16<<<agrid, 512, ATTN_SMEM>>>(nullptr);

    dim3 ogrid(DIM / 64, MROWS / 128);
    gemm_o<<<ogrid, 256, O_SMEM>>>(bo, out);
}